// round 10
// baseline (speedup 1.0000x reference)
#include <cuda_runtime.h>
#include <cstdint>
#include <cstddef>

#define T_STEPS 1024
#define BATCH   128
#define INDIM   100
#define HID     200
#define NCLS    100
#define NHG     17
#define NHU     12
#define NG      48
#define MB      8
#define NBG     16
#define NTHR    512
#define NCTA    (8*NHG)      // 136
#define W0ST    306          // [x:0-99 | pad:100-103 | hh:104-303 | pad]
#define W1ST    402
#define XPAD    104

#define HN_OFF  (T_STEPS*BATCH*NCLS)
#define CN_OFF  (HN_OFF + 2*BATCH*HID)

#define OFF_W0   0
#define OFF_W1   (OFF_W0 + NG*W0ST)          // 14688
#define OFF_XX   (OFF_W1 + NG*W1ST)          // 33984
#define OFF_XHA  (OFF_XX + XPAD*MB)          // 34816
#define OFF_XHB  (OFF_XHA + 400*MB)          // 38016
#define OFF_GB0A (OFF_XHB + 400*MB)          // 41216
#define OFF_GB0B (OFF_GB0A + 8*NG*MB)
#define OFF_GB1A (OFF_GB0B + 8*NG*MB)
#define OFF_GB1B (OFF_GB1A + 8*NG*MB)
#define OFF_XAA  (OFF_GB1B + 8*NG*MB)
#define OFF_XAB  (OFF_XAA + 4*NG*MB)
#define OFF_B0   (OFF_XAB + 4*NG*MB)
#define OFF_B1   (OFF_B0 + NG)
#define OFF_C0A  (OFF_B1 + NG)
#define OFF_C1A  (OFF_C0A + NHU*MB)
#define OFF_C0B  (OFF_C1A + NHU*MB)
#define OFF_C1B  (OFF_C0B + NHU*MB)
#define SMEM_FLOATS (OFF_C1B + NHU*MB + 32)  // 57088 -> 228,352 B
#define SMEM_BYTES  (SMEM_FLOATS*4)

#define OFF_FW  0
#define OFF_FB  20000
#define OFF_YS  20128

__device__ __align__(256) float g_ph0[2][HID*BATCH];
__device__ __align__(256) float g_ph1[2][HID*BATCH];
__device__ __align__(256) float g_y1[(size_t)T_STEPS*HID*BATCH];
__device__ unsigned g_bar[NBG*32];
__device__ unsigned g_gbar;
__device__ unsigned g_ack;

__device__ __forceinline__ float sigm(float x){ return __fdividef(1.0f, 1.0f + __expf(-x)); }
__device__ __forceinline__ float tanha(float x){ return fmaf(2.0f, sigm(2.0f*x), -1.0f); }
__device__ __forceinline__ void bar_arrive(unsigned* p){
    unsigned one=1u;
    asm volatile("red.release.gpu.global.add.u32 [%0], %1;" :: "l"(p), "r"(one) : "memory");
}
__device__ __forceinline__ unsigned ld_acq(const unsigned* p){
    unsigned v;
    asm volatile("ld.acquire.gpu.global.u32 %0, [%1];" : "=r"(v) : "l"(p) : "memory");
    return v;
}
__device__ __forceinline__ void cpa16(uint32_t dst, const void* src){
    asm volatile("cp.async.cg.shared.global [%0], [%1], 16;" :: "r"(dst), "l"(src) : "memory");
}
#define CPA_COMMIT() asm volatile("cp.async.commit_group;" ::: "memory")
#define CPA_WAIT0()  asm volatile("cp.async.wait_group 0;" ::: "memory")
#define STAGE_BAR()  asm volatile("bar.sync 1, 256;" ::: "memory")
#define FMA2(acc, w, x) asm("fma.rn.f32x2 %0, %1, %2, %0;" : "+l"(acc) : "l"(w), "l"(x))
__device__ __forceinline__ unsigned long long dup2(float s){
    unsigned long long d;
    asm("mov.b64 %0, {%1, %1};" : "=l"(d) : "f"(s));
    return d;
}

// gates[r0..r0+2][0..7] partial, k-chunk ks of length KH; x smem [k][8].
// ALIGNMENT: W float2 loads are only legal when the k-offset is even for all
// ks, i.e. KH even. For odd KH use scalar W loads (same bytes, LSU-cheap).
template<int KH, int WST>
__device__ __forceinline__ void gate_mm8(const float* __restrict__ W,
                                         const float* __restrict__ xp0,
                                         float* __restrict__ gbuf, int r0, int ks)
{
    const float* w0 = W + r0*WST + ks*KH;
    const float* w1 = w0 + WST;
    const float* w2 = w1 + WST;
    const float* xp = xp0 + ks*KH*MB;
    unsigned long long a[12];
    #pragma unroll
    for (int i = 0; i < 12; i++) a[i] = 0ull;
    constexpr int KE = KH & ~1;
    #pragma unroll 5
    for (int k = 0; k < KE; k += 2) {
        ulonglong2 x00 = *(const ulonglong2*)(xp + k*MB);
        ulonglong2 x01 = *(const ulonglong2*)(xp + k*MB + 4);
        ulonglong2 x10 = *(const ulonglong2*)(xp + (k+1)*MB);
        ulonglong2 x11 = *(const ulonglong2*)(xp + (k+1)*MB + 4);
        float wa0, wa1, wb0, wb1, wc0, wc1;
        if constexpr ((KH & 1) == 0) {
            float2 ta = *(const float2*)(w0 + k);
            float2 tb = *(const float2*)(w1 + k);
            float2 tc = *(const float2*)(w2 + k);
            wa0 = ta.x; wa1 = ta.y; wb0 = tb.x; wb1 = tb.y; wc0 = tc.x; wc1 = tc.y;
        } else {
            wa0 = w0[k]; wa1 = w0[k+1];
            wb0 = w1[k]; wb1 = w1[k+1];
            wc0 = w2[k]; wc1 = w2[k+1];
        }
        unsigned long long wax=dup2(wa0), wbx=dup2(wb0), wcx=dup2(wc0);
        FMA2(a[0],wax,x00.x); FMA2(a[1],wax,x00.y); FMA2(a[2],wax,x01.x); FMA2(a[3],wax,x01.y);
        FMA2(a[4],wbx,x00.x); FMA2(a[5],wbx,x00.y); FMA2(a[6],wbx,x01.x); FMA2(a[7],wbx,x01.y);
        FMA2(a[8],wcx,x00.x); FMA2(a[9],wcx,x00.y); FMA2(a[10],wcx,x01.x); FMA2(a[11],wcx,x01.y);
        unsigned long long way=dup2(wa1), wby=dup2(wb1), wcy=dup2(wc1);
        FMA2(a[0],way,x10.x); FMA2(a[1],way,x10.y); FMA2(a[2],way,x11.x); FMA2(a[3],way,x11.y);
        FMA2(a[4],wby,x10.x); FMA2(a[5],wby,x10.y); FMA2(a[6],wby,x11.x); FMA2(a[7],wby,x11.y);
        FMA2(a[8],wcy,x10.x); FMA2(a[9],wcy,x10.y); FMA2(a[10],wcy,x11.x); FMA2(a[11],wcy,x11.y);
    }
    if (KH & 1) {
        const int k = KE;
        ulonglong2 x00 = *(const ulonglong2*)(xp + k*MB);
        ulonglong2 x01 = *(const ulonglong2*)(xp + k*MB + 4);
        unsigned long long wax=dup2(w0[k]), wbx=dup2(w1[k]), wcx=dup2(w2[k]);
        FMA2(a[0],wax,x00.x); FMA2(a[1],wax,x00.y); FMA2(a[2],wax,x01.x); FMA2(a[3],wax,x01.y);
        FMA2(a[4],wbx,x00.x); FMA2(a[5],wbx,x00.y); FMA2(a[6],wbx,x01.x); FMA2(a[7],wbx,x01.y);
        FMA2(a[8],wcx,x00.x); FMA2(a[9],wcx,x00.y); FMA2(a[10],wcx,x01.x); FMA2(a[11],wcx,x01.y);
    }
    float* g = gbuf + ks*(NG*MB);
    *(ulonglong2*)(g + (r0+0)*MB)     = make_ulonglong2(a[0], a[1]);
    *(ulonglong2*)(g + (r0+0)*MB + 4) = make_ulonglong2(a[2], a[3]);
    *(ulonglong2*)(g + (r0+1)*MB)     = make_ulonglong2(a[4], a[5]);
    *(ulonglong2*)(g + (r0+1)*MB + 4) = make_ulonglong2(a[6], a[7]);
    *(ulonglong2*)(g + (r0+2)*MB)     = make_ulonglong2(a[8], a[9]);
    *(ulonglong2*)(g + (r0+2)*MB + 4) = make_ulonglong2(a[10], a[11]);
}

// pointwise at logical iter it: stid<96 layer0(step it), 128<=stid<224 layer1(step it-1)
__device__ __forceinline__ void pw_group(int it, int stid,
    const float* __restrict__ gb0, const float* __restrict__ gb1,
    const float* __restrict__ xac, float* __restrict__ c0s, float* __restrict__ c1s,
    const float* __restrict__ bias0, const float* __restrict__ bias1, int hs, int b0)
{
    if (it < T_STEPS && stid < 96) {
        int u = stid >> 3, b = stid & 7, j = hs + u;
        float gv[4];
        #pragma unroll
        for (int g = 0; g < 4; ++g) {
            int rr = g*NHU + u;
            float v = bias0[rr];
            #pragma unroll
            for (int s = 0; s < 8; ++s) v += gb0[s*(NG*MB) + rr*MB + b];
            #pragma unroll
            for (int s = 0; s < 4; ++s) v += xac[s*(NG*MB) + rr*MB + b];
            gv[g] = v;
        }
        float c = c0s[stid];
        c = sigm(gv[1])*c + sigm(gv[0])*tanha(gv[2]);
        float h = sigm(gv[3])*tanha(c);
        c0s[stid] = c;
        if (j < HID) g_ph0[it & 1][j*BATCH + b0 + b] = h;
    }
    if (it >= 1 && stid >= 128 && stid < 224) {
        int e = stid - 128, u = e >> 3, b = e & 7, j = hs + u;
        float gv[4];
        #pragma unroll
        for (int g = 0; g < 4; ++g) {
            int rr = g*NHU + u;
            float v = bias1[rr];
            #pragma unroll
            for (int s = 0; s < 8; ++s) v += gb1[s*(NG*MB) + rr*MB + b];
            gv[g] = v;
        }
        float c = c1s[e];
        c = sigm(gv[1])*c + sigm(gv[0])*tanha(gv[2]);
        float h = sigm(gv[3])*tanha(c);
        c1s[e] = c;
        if (j < HID) {
            g_ph1[it & 1][j*BATCH + b0 + b] = h;
            g_y1[(size_t)(it-1)*(HID*BATCH) + j*BATCH + b0 + b] = h;
        }
    }
}

// staging engine: finish step s-1, prepare step s for one group (256 threads)
__device__ __forceinline__ void stage_phase(int s, int stid, int hs, int b0,
    const float* __restrict__ W0s, float* __restrict__ xx,
    float* __restrict__ gb0, float* __restrict__ gb1, float* __restrict__ xac,
    float* __restrict__ c0s, float* __restrict__ c1s,
    const float* __restrict__ bias0, const float* __restrict__ bias1,
    unsigned* barG, const float* __restrict__ inp, uint32_t smb, int offxh)
{
    if (s >= 1)
        pw_group(s - 1, stid, gb0, gb1, xac, c0s, c1s, bias0, bias1, hs, b0);
    STAGE_BAR();
    if (s >= 1 && s <= T_STEPS && stid == 0) bar_arrive(barG);
    if (s < T_STEPS) {
        const float* xsrc = inp + (size_t)s*(BATCH*INDIM) + (size_t)b0*INDIM;
        for (int idx = stid; idx < MB*INDIM; idx += 256) {
            int b = idx / INDIM, k = idx - b*INDIM;
            xx[k*MB + b] = __ldg(xsrc + b*INDIM + k);
        }
    }
    if (s >= 1 && s <= T_STEPS && stid == 0) {
        unsigned tgt = (unsigned)s * NHG;
        while (ld_acq(barG) < tgt) {}
    }
    STAGE_BAR();
    if (s <= T_STEPS) {
        const float* ph0 = g_ph0[(s + 1) & 1];
        const float* ph1 = g_ph1[(s + 1) & 1];
        int tot = (s >= 1) ? 800 : 400;
        for (int idx = stid; idx < tot; idx += 256) {
            int a = idx >> 1, q = idx & 1;
            const float* src = (a < HID) ? (ph0 + a*BATCH + b0 + q*4)
                                         : (ph1 + (a-HID)*BATCH + b0 + q*4);
            cpa16(smb + (uint32_t)(offxh + a*MB + q*4)*4, src);
        }
        CPA_COMMIT();
    }
    if (s < T_STEPS && stid < 64)
        gate_mm8<26, W0ST>(W0s, xx, xac, (stid & 15)*3, stid >> 4);
    if (s <= T_STEPS) CPA_WAIT0();
}

__global__ void __launch_bounds__(NTHR, 1)
lstm_all_kernel(const float* __restrict__ inp,  const float* __restrict__ h0in,
                const float* __restrict__ c0in,
                const float* __restrict__ Wih0, const float* __restrict__ Whh0,
                const float* __restrict__ bih0, const float* __restrict__ bhh0,
                const float* __restrict__ Wih1, const float* __restrict__ Whh1,
                const float* __restrict__ bih1, const float* __restrict__ bhh1,
                const float* __restrict__ fcW,  const float* __restrict__ fcb,
                float* __restrict__ out)
{
    extern __shared__ float sm[];
    float* W0s = sm + OFF_W0;  float* W1s = sm + OFF_W1;
    float* xx  = sm + OFF_XX;
    float* xhA = sm + OFF_XHA; float* xhB = sm + OFF_XHB;
    float* gb0A= sm + OFF_GB0A;float* gb0B= sm + OFF_GB0B;
    float* gb1A= sm + OFF_GB1A;float* gb1B= sm + OFF_GB1B;
    float* xacA= sm + OFF_XAA; float* xacB= sm + OFF_XAB;
    float* bias0 = sm + OFF_B0; float* bias1 = sm + OFF_B1;
    float* c0A = sm + OFF_C0A; float* c1A = sm + OFF_C1A;
    float* c0B = sm + OFF_C0B; float* c1B = sm + OFF_C1B;

    const int tid  = threadIdx.x;
    const int pair = blockIdx.x / NHG;
    const int hg   = blockIdx.x % NHG;
    const int hs   = hg * NHU;
    const int b0A  = (pair*2) * MB, b0B = (pair*2+1) * MB;
    unsigned* barA = &g_bar[(pair*2) * 32];
    unsigned* barB = &g_bar[(pair*2+1) * 32];
    const uint32_t smb = (uint32_t)__cvta_generic_to_shared(sm);
    const int r0m = (tid & 15) * 3;
    const int ksm = (tid >> 4) & 7;

    for (int i = tid; i < NG*W0ST; i += NTHR) {
        int c = i / W0ST, k = i - c*W0ST;
        int gate = c / NHU, u = c - gate*NHU;
        int j = hs + u, row = gate*HID + j;
        float v = 0.f;
        if (j < HID) {
            if (k < INDIM) v = Wih0[row*INDIM + k];
            else if (k >= XPAD && k < XPAD + HID) v = Whh0[row*HID + (k - XPAD)];
        }
        W0s[c*W0ST + k] = v;
    }
    for (int i = tid; i < NG*W1ST; i += NTHR) {
        int c = i / W1ST, k = i - c*W1ST;
        int gate = c / NHU, u = c - gate*NHU;
        int j = hs + u, row = gate*HID + j;
        float v = 0.f;
        if (j < HID && k < 400) v = (k < HID) ? Wih1[row*HID + k] : Whh1[row*HID + (k - HID)];
        W1s[c*W1ST + k] = v;
    }
    if (tid < NG) {
        int gate = tid / NHU, u = tid - gate*NHU;
        int j = hs + u, row = gate*HID + j;
        bias0[tid] = (j < HID) ? bih0[row] + bhh0[row] : 0.f;
        bias1[tid] = (j < HID) ? bih1[row] + bhh1[row] : 0.f;
    }
    if (tid < 32) xx[(INDIM + (tid >> 3))*MB + (tid & 7)] = 0.f;   // zero pad rows 100-103

    if (tid < 192) {
        int G = tid / 96, e = tid - G*96;
        int u = e >> 3, b = e & 7, j = hs + u;
        int b0 = G ? b0B : b0A;
        float* c0s = G ? c0B : c0A;
        float* c1s = G ? c1B : c1A;
        float cv0 = 0.f, cv1 = 0.f;
        if (j < HID) {
            cv0 = c0in[(b0 + b)*HID + j];
            cv1 = c0in[BATCH*HID + (b0 + b)*HID + j];
            g_ph0[1][j*BATCH + b0 + b] = h0in[(b0 + b)*HID + j];
            g_ph1[0][j*BATCH + b0 + b] = h0in[BATCH*HID + (b0 + b)*HID + j];
        }
        c0s[e] = cv0; c1s[e] = cv1;
    }
    __syncthreads();
    if (tid == 0) {
        bar_arrive(&g_gbar);
        while (ld_acq(&g_gbar) < NCTA) {}
    }
    __syncthreads();

    // prologue: prep A(0)
    {
        const float* xsrc = inp + (size_t)b0A*INDIM;
        for (int idx = tid; idx < MB*INDIM; idx += NTHR) {
            int b = idx / INDIM, k = idx - b*INDIM;
            xx[k*MB + b] = __ldg(xsrc + b*INDIM + k);
        }
    }
    __syncthreads();
    if (tid < 64) gate_mm8<26, W0ST>(W0s, xx, xacA, (tid & 15)*3, tid >> 4);
    {
        const float* ph0 = g_ph0[1];
        for (int idx = tid; idx < 400; idx += NTHR) {
            int a = idx >> 1, q = idx & 1;
            cpa16(smb + (uint32_t)(OFF_XHA + a*MB + q*4)*4, ph0 + a*BATCH + b0A + q*4);
        }
        CPA_COMMIT(); CPA_WAIT0();
    }
    __syncthreads();

    for (int t = 0; t <= T_STEPS; ++t) {
        // PHASE 1: mm A(t) || stage B(t)
        if (tid < 256) {
            if (tid < 128) { if (t >= 1) gate_mm8<50, W1ST>(W1s, xhA, gb1A, r0m, ksm); }
            else           { if (t < T_STEPS) gate_mm8<25, W0ST>(W0s + XPAD, xhA, gb0A, r0m, ksm); }
        } else {
            stage_phase(t, tid - 256, hs, b0B, W0s, xx, gb0B, gb1B, xacB,
                        c0B, c1B, bias0, bias1, barB, inp, smb, OFF_XHB);
        }
        __syncthreads();
        // PHASE 2: mm B(t) || stage A(t+1)
        if (tid < 256) {
            if (tid < 128) { if (t >= 1) gate_mm8<50, W1ST>(W1s, xhB, gb1B, r0m, ksm); }
            else           { if (t < T_STEPS) gate_mm8<25, W0ST>(W0s + XPAD, xhB, gb0B, r0m, ksm); }
        } else {
            stage_phase(t + 1, tid - 256, hs, b0A, W0s, xx, gb0A, gb1A, xacA,
                        c0A, c1A, bias0, bias1, barA, inp, smb, OFF_XHA);
        }
        __syncthreads();
    }
    // final pointwise for B at it=T_STEPS
    if (tid >= 256)
        pw_group(T_STEPS, tid - 256, gb0B, gb1B, xacB, c0B, c1B, bias0, bias1, hs, b0B);
    __syncthreads();

    // epilogue: hn, cn for both groups
    if (tid < 192) {
        int G = tid / 96, e = tid - G*96;
        int u = e >> 3, b = e & 7, j = hs + u;
        int b0 = G ? b0B : b0A;
        const float* c0s = G ? c0B : c0A;
        const float* c1s = G ? c1B : c1A;
        if (j < HID) {
            out[HN_OFF + (b0 + b)*HID + j]             = __ldcg(&g_ph0[(T_STEPS-1)&1][j*BATCH + b0 + b]);
            out[HN_OFF + BATCH*HID + (b0 + b)*HID + j] = __ldcg(&g_ph1[T_STEPS&1][j*BATCH + b0 + b]);
            out[CN_OFF + (b0 + b)*HID + j]             = c0s[e];
            out[CN_OFF + BATCH*HID + (b0 + b)*HID + j] = c1s[e];
        }
    }
    __syncthreads();

    if (tid == 0) {
        bar_arrive(&g_gbar);
        while (ld_acq(&g_gbar) < 2*NCTA) {}
    }
    __syncthreads();

    // FC: out[t,b,c] = fcb[c] + sum_h fcW[c][h] * y1[t,h,b]
    {
        float* fws = sm + OFF_FW;
        float* fbs = sm + OFF_FB;
        float* ys  = sm + OFF_YS;
        for (int i = tid; i < NCLS*HID; i += NTHR) fws[i] = fcW[i];
        if (tid < NCLS) fbs[tid] = fcb[tid];
        __syncthreads();
        const int bqf = (tid & 31)*4;
        const int cg  = tid >> 5;
        for (int tt = 0; tt < 8; ++tt) {
            int t = blockIdx.x*8 + tt;
            if (t >= T_STEPS) break;
            const float* y = g_y1 + (size_t)t*(HID*BATCH);
            float acc[2][4][4];
            #pragma unroll
            for (int qi = 0; qi < 2; qi++) {
                int cq = cg + 16*qi;
                #pragma unroll
                for (int jc = 0; jc < 4; jc++) {
                    float bv = (cq < 25) ? fbs[cq*4 + jc] : 0.f;
                    #pragma unroll
                    for (int jb = 0; jb < 4; jb++) acc[qi][jc][jb] = bv;
                }
            }
            for (int kc = 0; kc < 4; ++kc) {
                __syncthreads();
                for (int i = tid; i < 50*32; i += NTHR) {
                    int k = i >> 5, q = i & 31;
                    *(float4*)&ys[k*128 + q*4] =
                        __ldcg((const float4*)(y + (size_t)(kc*50 + k)*BATCH + q*4));
                }
                __syncthreads();
                for (int k = 0; k < 50; ++k) {
                    float4 yv = *(const float4*)&ys[k*128 + bqf];
                    #pragma unroll
                    for (int qi = 0; qi < 2; qi++) {
                        int cq = cg + 16*qi;
                        if (cq < 25) {
                            #pragma unroll
                            for (int jc = 0; jc < 4; jc++) {
                                float w = fws[(cq*4 + jc)*HID + kc*50 + k];
                                acc[qi][jc][0] = fmaf(w, yv.x, acc[qi][jc][0]);
                                acc[qi][jc][1] = fmaf(w, yv.y, acc[qi][jc][1]);
                                acc[qi][jc][2] = fmaf(w, yv.z, acc[qi][jc][2]);
                                acc[qi][jc][3] = fmaf(w, yv.w, acc[qi][jc][3]);
                            }
                        }
                    }
                }
            }
            float* o = out + (size_t)t*BATCH*NCLS;
            #pragma unroll
            for (int qi = 0; qi < 2; qi++) {
                int cq = cg + 16*qi;
                if (cq < 25) {
                    #pragma unroll
                    for (int jb = 0; jb < 4; jb++) {
                        float4 v = make_float4(acc[qi][0][jb], acc[qi][1][jb],
                                               acc[qi][2][jb], acc[qi][3][jb]);
                        *(float4*)(o + (bqf + jb)*NCLS + cq*4) = v;
                    }
                }
            }
        }
    }

    __syncthreads();
    if (tid == 0) {
        bar_arrive(&g_ack);
        if (blockIdx.x == 0) {
            while (ld_acq(&g_ack) < NCTA) {}
            for (int i = 0; i < NBG; i++) *(volatile unsigned*)&g_bar[i*32] = 0u;
            *(volatile unsigned*)&g_gbar = 0u;
            *(volatile unsigned*)&g_ack  = 0u;
        }
    }
}

extern "C" void kernel_launch(void* const* d_in, const int* in_sizes, int n_in,
                              void* d_out, int out_size)
{
    (void)in_sizes; (void)n_in; (void)out_size;
    const float* inp  = (const float*)d_in[0];
    const float* h0   = (const float*)d_in[1];
    const float* c0   = (const float*)d_in[2];
    const float* Wih0 = (const float*)d_in[3];
    const float* Whh0 = (const float*)d_in[4];
    const float* bih0 = (const float*)d_in[5];
    const float* bhh0 = (const float*)d_in[6];
    const float* Wih1 = (const float*)d_in[7];
    const float* Whh1 = (const float*)d_in[8];
    const float* bih1 = (const float*)d_in[9];
    const float* bhh1 = (const float*)d_in[10];
    const float* fcW  = (const float*)d_in[11];
    const float* fcb  = (const float*)d_in[12];
    float* out = (float*)d_out;

    cudaFuncSetAttribute(lstm_all_kernel,
                         cudaFuncAttributeMaxDynamicSharedMemorySize, SMEM_BYTES);
    lstm_all_kernel<<<NCTA, NTHR, SMEM_BYTES>>>(inp, h0, c0,
                                                Wih0, Whh0, bih0, bhh0,
                                                Wih1, Whh1, bih1, bhh1,
                                                fcW, fcb, out);
}

// round 11
// speedup vs baseline: 1.0510x; 1.0510x over previous
#include <cuda_runtime.h>
#include <cstdint>
#include <cstddef>

#define T_STEPS 1024
#define BATCH   128
#define INDIM   100
#define HID     200
#define NCLS    100
#define NBG     8           // batch groups
#define MB      16          // batch per group
#define NHG     17          // hidden groups per batch group
#define NHU     12          // hidden units per CTA
#define NG      48          // gate rows per CTA
#define NTHR    512
#define NCTA    (NBG*NHG)   // 136
#define XSTR    20          // smem stride of [k][b] staging buffer
#define GRS     18          // gb row stride (padded, conflict-free)
#define GBS     (NG*GRS)    // 864 floats per ksplit block

#define HN_OFF  (T_STEPS*BATCH*NCLS)
#define CN_OFF  (HN_OFF + 2*BATCH*HID)

// ---- smem float offsets ----
#define OFF_W0  0                        // W0 transposed [300][48]
#define OFF_W1  14400                    // W1 transposed [400][48]
#define OFF_XH  33600                    // [500][XSTR]
#define OFF_GB0 43600                    // [4][GBS]
#define OFF_GB1 47056                    // [8][GBS]
#define OFF_XA  53968                    // [2][GBS]
#define OFF_B0  55696
#define OFF_B1  55744
#define OFF_C0  55792                    // [NHU][MB]
#define OFF_C1  55984
#define SMEM_FLOATS 56192
#define SMEM_BYTES  (SMEM_FLOATS*4)      // 224,768 B

// FC-phase smem reuse
#define OFF_FW  0        // [100][200]
#define OFF_FB  20000
#define OFF_YS  20128    // [50][128]

// -------- device scratch --------
__device__ __align__(256) float g_ph0[2][HID*BATCH];
__device__ __align__(256) float g_ph1[2][HID*BATCH];
__device__ __align__(256) float g_y1[(size_t)T_STEPS*HID*BATCH];
__device__ unsigned g_bar[NBG*32];
__device__ unsigned g_gbar;
__device__ unsigned g_ack;

__device__ __forceinline__ float sigm(float x) {
    return __fdividef(1.0f, 1.0f + __expf(-x));
}
__device__ __forceinline__ float tanha(float x) {
    return fmaf(2.0f, sigm(2.0f * x), -1.0f);
}

__device__ __forceinline__ void bar_arrive(unsigned* p) {
    unsigned one = 1u;
    asm volatile("red.release.gpu.global.add.u32 [%0], %1;" :: "l"(p), "r"(one) : "memory");
}
__device__ __forceinline__ unsigned ld_acq(const unsigned* p) {
    unsigned v;
    asm volatile("ld.acquire.gpu.global.u32 %0, [%1];" : "=r"(v) : "l"(p) : "memory");
    return v;
}
__device__ __forceinline__ void cpa16(uint32_t dst, const void* src) {
    asm volatile("cp.async.cg.shared.global [%0], [%1], 16;" :: "r"(dst), "l"(src) : "memory");
}
__device__ __forceinline__ void cpa_wait() {
    asm volatile("cp.async.commit_group;\n\tcp.async.wait_group 0;" ::: "memory");
}

// packed f32x2 helpers
#define FMA2(acc, w, x) \
    asm("fma.rn.f32x2 %0, %1, %2, %0;" : "+l"(acc) : "l"(w), "l"(x))
__device__ __forceinline__ unsigned long long pk2(unsigned lo, unsigned hi) {
    unsigned long long d;
    asm("mov.b64 %0, {%1, %2};" : "=l"(d) : "r"(lo), "r"(hi));
    return d;
}
__device__ __forceinline__ void upk2(unsigned long long v, unsigned& lo, unsigned& hi) {
    asm("mov.b64 {%0, %1}, %2;" : "=r"(lo), "=r"(hi) : "l"(v));
}

// Diagonal-pair FFMA2 mm: W transposed [k][48] (adjacent rows = native pair),
// x [k][b] (adjacent batches = native pair). Thread tile: 3 row-pairs x 2 batches.
//   diag acc = {(r,b),(r+1,b+1)}, anti acc = {(r,b+1),(r+1,b)}
// w: Wt + kbase*48 + 6*rpg ; xp: xh + kbase*XSTR + 2*bq2 ;
// gp: gbuf + ks*GBS + 6*rpg*GRS + 2*bq2
template<int KH>
__device__ __forceinline__ void gate_mmT(const float* __restrict__ w,
                                         const float* __restrict__ xp,
                                         float* __restrict__ gp)
{
    unsigned long long d0=0ull, a0=0ull, d1=0ull, a1=0ull, d2=0ull, a2=0ull;
    #pragma unroll 5
    for (int k = 0; k < KH; ++k) {
        uint2 xv = *(const uint2*)(xp + k * XSTR);
        unsigned long long xd = pk2(xv.x, xv.y);
        unsigned long long xs = pk2(xv.y, xv.x);
        unsigned long long w0 = *(const unsigned long long*)(w + k * 48);
        unsigned long long w1 = *(const unsigned long long*)(w + k * 48 + 2);
        unsigned long long w2 = *(const unsigned long long*)(w + k * 48 + 4);
        FMA2(d0, w0, xd); FMA2(a0, w0, xs);
        FMA2(d1, w1, xd); FMA2(a1, w1, xs);
        FMA2(d2, w2, xd); FMA2(a2, w2, xs);
    }
    // re-pair to row-major {b, b+1} and store
    unsigned dl, dh, al, ah;
    upk2(d0, dl, dh); upk2(a0, al, ah);
    *(unsigned long long*)(gp + 0 * GRS) = pk2(dl, al);
    *(unsigned long long*)(gp + 1 * GRS) = pk2(ah, dh);
    upk2(d1, dl, dh); upk2(a1, al, ah);
    *(unsigned long long*)(gp + 2 * GRS) = pk2(dl, al);
    *(unsigned long long*)(gp + 3 * GRS) = pk2(ah, dh);
    upk2(d2, dl, dh); upk2(a2, al, ah);
    *(unsigned long long*)(gp + 4 * GRS) = pk2(dl, al);
    *(unsigned long long*)(gp + 5 * GRS) = pk2(ah, dh);
}

__global__ void __launch_bounds__(NTHR, 1)
lstm_all_kernel(const float* __restrict__ inp,  const float* __restrict__ h0in,
                const float* __restrict__ c0in,
                const float* __restrict__ Wih0, const float* __restrict__ Whh0,
                const float* __restrict__ bih0, const float* __restrict__ bhh0,
                const float* __restrict__ Wih1, const float* __restrict__ Whh1,
                const float* __restrict__ bih1, const float* __restrict__ bhh1,
                const float* __restrict__ fcW,  const float* __restrict__ fcb,
                float* __restrict__ out)
{
    extern __shared__ float sm[];
    float* W0t   = sm + OFF_W0;   // [300][48] transposed
    float* W1t   = sm + OFF_W1;   // [400][48] transposed
    float* xh    = sm + OFF_XH;   // [500][XSTR]
    float* gb0   = sm + OFF_GB0;
    float* gb1   = sm + OFF_GB1;
    float* xac   = sm + OFF_XA;
    float* bias0 = sm + OFF_B0;
    float* bias1 = sm + OFF_B1;
    float* c0s   = sm + OFF_C0;
    float* c1s   = sm + OFF_C1;

    const int tid = threadIdx.x;
    const int bg  = blockIdx.x / NHG;
    const int hg  = blockIdx.x % NHG;
    const int b0  = bg * MB;
    const int hs  = hg * NHU;
    const uint32_t smb = (uint32_t)__cvta_generic_to_shared(sm);

    // mm decode: cell 0..63 -> 8 row-pair-groups (6 rows) x 8 batch-pairs; ks = tid>>6
    const int cell = tid & 63;
    const int bq2  = cell & 7;            // batches {2bq2, 2bq2+1}
    const int rpg  = cell >> 3;           // rows 6rpg .. 6rpg+5
    const int ksp  = tid >> 6;            // 0..7
    const int wofs = 6 * rpg;             // word offset of first row-pair
    const int gofs = 6 * rpg * GRS + 2 * bq2;

    // ---- resident weight slices (TRANSPOSED [k][48]) ----
    for (int i = tid; i < NG * 300; i += NTHR) {
        int c = i / 300, k = i - c * 300;
        int gate = c / NHU, u = c - gate * NHU;
        int j = hs + u, row = gate * HID + j;
        float v = 0.f;
        if (j < HID) v = (k < INDIM) ? Wih0[row * INDIM + k] : Whh0[row * HID + (k - INDIM)];
        W0t[k * 48 + c] = v;
    }
    for (int i = tid; i < NG * 400; i += NTHR) {
        int c = i / 400, k = i - c * 400;
        int gate = c / NHU, u = c - gate * NHU;
        int j = hs + u, row = gate * HID + j;
        float v = 0.f;
        if (j < HID) v = (k < HID) ? Wih1[row * HID + k] : Whh1[row * HID + (k - HID)];
        W1t[k * 48 + c] = v;
    }
    if (tid < NG) {
        int gate = tid / NHU, u = tid - gate * NHU;
        int j = hs + u, row = gate * HID + j;
        bias0[tid] = (j < HID) ? bih0[row] + bhh0[row] : 0.f;
        bias1[tid] = (j < HID) ? bih1[row] + bhh1[row] : 0.f;
    }

    // ---- init c state, publish initial h ----
    if (tid < NHU * MB) {
        int e = tid, u = e >> 4, b = e & 15, j = hs + u;
        float cv0 = 0.f, cv1 = 0.f;
        if (j < HID) {
            cv0 = c0in[(b0 + b) * HID + j];
            cv1 = c0in[BATCH * HID + (b0 + b) * HID + j];
            g_ph0[1][j * BATCH + b0 + b] = h0in[(b0 + b) * HID + j];
            g_ph1[0][j * BATCH + b0 + b] = h0in[BATCH * HID + (b0 + b) * HID + j];
        }
        c0s[e] = cv0;
        c1s[e] = cv1;
    }

    // ---- prologue: stage x(0), xacc(0) ----
    {
        const float* xsrc = inp + (size_t)b0 * INDIM;
        for (int idx = tid; idx < MB * INDIM; idx += NTHR) {
            int b = idx / INDIM, k = idx - b * INDIM;
            xh[k * XSTR + b] = __ldg(xsrc + b * INDIM + k);
        }
    }
    __syncthreads();
    if (tid < 128)
        gate_mmT<50>(W0t + ksp * 50 * 48 + wofs, xh + ksp * 50 * XSTR + 2 * bq2,
                     xac + ksp * GBS + gofs);
    __syncthreads();

    unsigned* gbar = &g_bar[bg * 32];
    unsigned ep = 1;
    if (tid == 0) {
        bar_arrive(gbar);
        while (ld_acq(gbar) < ep * NHG) {}
    }
    __syncthreads();

    // ---- main loop: iter it = layer0(step it) + layer1(step it-1) ----
    for (int it = 0; it <= T_STEPS; ++it) {
        // async-stage h0(it-1) -> rows 100-299, h1(it-2) -> rows 300-499
        {
            const float* ph0 = g_ph0[(it + 1) & 1];
            const float* ph1 = g_ph1[(it + 1) & 1];
            int tot = (it >= 1) ? 1600 : 800;
            for (int idx = tid; idx < tot; idx += NTHR) {
                int a = idx >> 2, q = idx & 3;
                const float* src = (a < HID) ? (ph0 + a * BATCH)
                                             : (ph1 + (a - HID) * BATCH);
                cpa16(smb + (OFF_XH + (INDIM + a) * XSTR + q * 4) * 4,
                      src + b0 + q * 4);
            }
            cpa_wait();
        }
        __syncthreads();

        if (it < T_STEPS && tid < 256)        // layer0 hh: K=200, ks 0..3
            gate_mmT<50>(W0t + (INDIM + ksp * 50) * 48 + wofs,
                         xh + (INDIM + ksp * 50) * XSTR + 2 * bq2,
                         gb0 + ksp * GBS + gofs);
        if (it >= 1)                          // layer1 full: K=400, ks 0..7
            gate_mmT<50>(W1t + ksp * 50 * 48 + wofs,
                         xh + (INDIM + ksp * 50) * XSTR + 2 * bq2,
                         gb1 + ksp * GBS + gofs);
        __syncthreads();

        // ---- pointwise (layer0 on t<192, layer1 on 192<=t<384) ----
        if (it < T_STEPS && tid < 192) {
            int e = tid, u = e >> 4, b = e & 15, j = hs + u;
            float gv[4];
            #pragma unroll
            for (int g = 0; g < 4; ++g) {
                int rr = g * NHU + u;
                float v = bias0[rr];
                #pragma unroll
                for (int s = 0; s < 4; ++s) v += gb0[s * GBS + rr * GRS + b];
                v += xac[rr * GRS + b] + xac[GBS + rr * GRS + b];
                gv[g] = v;
            }
            float c = c0s[e];
            c = sigm(gv[1]) * c + sigm(gv[0]) * tanha(gv[2]);
            float h = sigm(gv[3]) * tanha(c);
            c0s[e] = c;
            if (j < HID) g_ph0[it & 1][j * BATCH + b0 + b] = h;
        }
        if (it >= 1 && tid >= 192 && tid < 384) {
            int e = tid - 192, u = e >> 4, b = e & 15, j = hs + u;
            float gv[4];
            #pragma unroll
            for (int g = 0; g < 4; ++g) {
                int rr = g * NHU + u;
                float v = bias1[rr];
                #pragma unroll
                for (int s = 0; s < 8; ++s) v += gb1[s * GBS + rr * GRS + b];
                gv[g] = v;
            }
            float c = c1s[e];
            c = sigm(gv[1]) * c + sigm(gv[0]) * tanha(gv[2]);
            float h = sigm(gv[3]) * tanha(c);
            c1s[e] = c;
            if (j < HID) {
                g_ph1[it & 1][j * BATCH + b0 + b] = h;
                g_y1[(size_t)(it - 1) * HID * BATCH + j * BATCH + b0 + b] = h;
            }
        }
        if (it == T_STEPS) break;
        __syncthreads();

        ep++;
        if (tid == 0) bar_arrive(gbar);

        // ---- barrier-shadow: stage x(it+1), xacc(it+1) ----
        if (it + 1 < T_STEPS) {
            const float* xsrc = inp + (size_t)(it + 1) * BATCH * INDIM + (size_t)b0 * INDIM;
            for (int idx = tid; idx < MB * INDIM; idx += NTHR) {
                int b = idx / INDIM, k = idx - b * INDIM;
                xh[k * XSTR + b] = __ldg(xsrc + b * INDIM + k);
            }
            __syncthreads();
            if (tid < 128)
                gate_mmT<50>(W0t + ksp * 50 * 48 + wofs, xh + ksp * 50 * XSTR + 2 * bq2,
                             xac + ksp * GBS + gofs);
        }

        if (tid == 0) { while (ld_acq(gbar) < ep * NHG) {} }
        __syncthreads();
    }

    // Final layer1 pointwise (tid 192-383) must be visible to epilogue readers.
    __syncthreads();

    // ---- epilogue: hn, cn ----
    if (tid < NHU * MB) {
        int e = tid, u = e >> 4, b = e & 15, j = hs + u;
        if (j < HID) {
            out[HN_OFF + (b0 + b) * HID + j]               = __ldcg(&g_ph0[(T_STEPS - 1) & 1][j * BATCH + b0 + b]);
            out[HN_OFF + BATCH * HID + (b0 + b) * HID + j] = __ldcg(&g_ph1[T_STEPS & 1][j * BATCH + b0 + b]);
            out[CN_OFF + (b0 + b) * HID + j]               = c0s[e];
            out[CN_OFF + BATCH * HID + (b0 + b) * HID + j] = c1s[e];
        }
    }
    __syncthreads();

    // ---- global barrier before FC ----
    if (tid == 0) {
        bar_arrive(&g_gbar);
        while (ld_acq(&g_gbar) < NCTA) {}
    }
    __syncthreads();

    // ---- FC phase: out[t,b,c] = fcb[c] + sum_h fcW[c][h] * y1[t,h,b] ----
    {
        float* fws = sm + OFF_FW;
        float* fbs = sm + OFF_FB;
        float* ys  = sm + OFF_YS;
        for (int i = tid; i < NCLS * HID; i += NTHR) fws[i] = fcW[i];
        if (tid < NCLS) fbs[tid] = fcb[tid];
        __syncthreads();

        const int bqf = (tid & 31) * 4;
        const int cg  = tid >> 5;              // 0..15
        for (int tt = 0; tt < 8; ++tt) {
            int t = blockIdx.x * 8 + tt;
            if (t >= T_STEPS) break;
            const float* y = g_y1 + (size_t)t * HID * BATCH;
            float acc[2][4][4];
            #pragma unroll
            for (int qi = 0; qi < 2; qi++) {
                int cq = cg + 16 * qi;
                #pragma unroll
                for (int jc = 0; jc < 4; jc++) {
                    float bv = (cq < 25) ? fbs[cq * 4 + jc] : 0.f;
                    #pragma unroll
                    for (int jb = 0; jb < 4; jb++) acc[qi][jc][jb] = bv;
                }
            }
            for (int kc = 0; kc < 4; ++kc) {
                __syncthreads();
                for (int i = tid; i < 50 * 32; i += NTHR) {
                    int k = i >> 5, q = i & 31;
                    *(float4*)&ys[k * 128 + q * 4] =
                        __ldcg((const float4*)(y + (size_t)(kc * 50 + k) * BATCH + q * 4));
                }
                __syncthreads();
                for (int k = 0; k < 50; ++k) {
                    float4 yv = *(const float4*)&ys[k * 128 + bqf];
                    #pragma unroll
                    for (int qi = 0; qi < 2; qi++) {
                        int cq = cg + 16 * qi;
                        if (cq < 25) {
                            #pragma unroll
                            for (int jc = 0; jc < 4; jc++) {
                                float w = fws[(cq * 4 + jc) * HID + kc * 50 + k];
                                acc[qi][jc][0] = fmaf(w, yv.x, acc[qi][jc][0]);
                                acc[qi][jc][1] = fmaf(w, yv.y, acc[qi][jc][1]);
                                acc[qi][jc][2] = fmaf(w, yv.z, acc[qi][jc][2]);
                                acc[qi][jc][3] = fmaf(w, yv.w, acc[qi][jc][3]);
                            }
                        }
                    }
                }
            }
            float* o = out + (size_t)t * BATCH * NCLS;
            #pragma unroll
            for (int qi = 0; qi < 2; qi++) {
                int cq = cg + 16 * qi;
                if (cq < 25) {
                    #pragma unroll
                    for (int jb = 0; jb < 4; jb++) {
                        float4 v = make_float4(acc[qi][0][jb], acc[qi][1][jb],
                                               acc[qi][2][jb], acc[qi][3][jb]);
                        *(float4*)(o + (bqf + jb) * NCLS + cq * 4) = v;
                    }
                }
            }
        }
    }

    // ---- reset-free counter cleanup ----
    __syncthreads();
    if (tid == 0) {
        bar_arrive(&g_ack);
        if (blockIdx.x == 0) {
            while (ld_acq(&g_ack) < NCTA) {}
            for (int i = 0; i < NBG; i++) *(volatile unsigned*)&g_bar[i * 32] = 0u;
            *(volatile unsigned*)&g_gbar = 0u;
            *(volatile unsigned*)&g_ack  = 0u;
        }
    }
}

extern "C" void kernel_launch(void* const* d_in, const int* in_sizes, int n_in,
                              void* d_out, int out_size)
{
    (void)in_sizes; (void)n_in; (void)out_size;
    const float* inp  = (const float*)d_in[0];
    const float* h0   = (const float*)d_in[1];
    const float* c0   = (const float*)d_in[2];
    const float* Wih0 = (const float*)d_in[3];
    const float* Whh0 = (const float*)d_in[4];
    const float* bih0 = (const float*)d_in[5];
    const float* bhh0 = (const float*)d_in[6];
    const float* Wih1 = (const float*)d_in[7];
    const float* Whh1 = (const float*)d_in[8];
    const float* bih1 = (const float*)d_in[9];
    const float* bhh1 = (const float*)d_in[10];
    const float* fcW  = (const float*)d_in[11];
    const float* fcb  = (const float*)d_in[12];
    float* out = (float*)d_out;

    cudaFuncSetAttribute(lstm_all_kernel,
                         cudaFuncAttributeMaxDynamicSharedMemorySize, SMEM_BYTES);
    lstm_all_kernel<<<NCTA, NTHR, SMEM_BYTES>>>(inp, h0, c0,
                                                Wih0, Whh0, bih0, bhh0,
                                                Wih1, Whh1, bih1, bhh1,
                                                fcW, fcb, out);
}

// round 12
// speedup vs baseline: 1.0859x; 1.0333x over previous
#include <cuda_runtime.h>
#include <cstdint>
#include <cstddef>

#define T_STEPS 1024
#define BATCH   128
#define INDIM   100
#define HID     200
#define NCLS    100
#define NBG     8
#define MB      16
#define NHG     17
#define NHU     12
#define NG      48
#define NTHR    768
#define NCTA    (NBG*NHG)   // 136
#define XSTR    20
#define GRS     18
#define GBS     (NG*GRS)    // 864

#define HN_OFF  (T_STEPS*BATCH*NCLS)
#define CN_OFF  (HN_OFF + 2*BATCH*HID)

// ---- smem float offsets ----
#define OFF_W0  0                        // W0 transposed [300][48]
#define OFF_W1  14400                    // W1 transposed [400][48]
#define OFF_XH  33600                    // [500][XSTR]
#define OFF_GB0 43600                    // [4][GBS]
#define OFF_GB1 47056                    // [8][GBS]
#define OFF_XA  53968                    // [2][GBS]
#define OFF_B0  55696
#define OFF_B1  55744
#define OFF_C0  55792
#define OFF_C1  55984
#define SMEM_FLOATS 56192
#define SMEM_BYTES  (SMEM_FLOATS*4)      // 224,768 B (same as r11)

// FC-phase smem reuse
#define OFF_FW  0
#define OFF_FB  20000
#define OFF_YS  20128

__device__ __align__(256) float g_ph0[2][HID*BATCH];
__device__ __align__(256) float g_ph1[2][HID*BATCH];
__device__ __align__(256) float g_y1[(size_t)T_STEPS*HID*BATCH];
__device__ unsigned g_bar[NBG*32];
__device__ unsigned g_gbar;
__device__ unsigned g_ack;

__device__ __forceinline__ float sigm(float x) {
    return __fdividef(1.0f, 1.0f + __expf(-x));
}
__device__ __forceinline__ float tanha(float x) {
    return fmaf(2.0f, sigm(2.0f * x), -1.0f);
}
__device__ __forceinline__ void bar_arrive(unsigned* p) {
    unsigned one = 1u;
    asm volatile("red.release.gpu.global.add.u32 [%0], %1;" :: "l"(p), "r"(one) : "memory");
}
__device__ __forceinline__ unsigned ld_acq(const unsigned* p) {
    unsigned v;
    asm volatile("ld.acquire.gpu.global.u32 %0, [%1];" : "=r"(v) : "l"(p) : "memory");
    return v;
}
__device__ __forceinline__ void cpa16(uint32_t dst, const void* src) {
    asm volatile("cp.async.cg.shared.global [%0], [%1], 16;" :: "r"(dst), "l"(src) : "memory");
}
__device__ __forceinline__ void cpa_wait() {
    asm volatile("cp.async.commit_group;\n\tcp.async.wait_group 0;" ::: "memory");
}

#define FMA2(acc, w, x) \
    asm("fma.rn.f32x2 %0, %1, %2, %0;" : "+l"(acc) : "l"(w), "l"(x))
__device__ __forceinline__ unsigned long long pk2(unsigned lo, unsigned hi) {
    unsigned long long d;
    asm("mov.b64 %0, {%1, %2};" : "=l"(d) : "r"(lo), "r"(hi));
    return d;
}
__device__ __forceinline__ void upk2(unsigned long long v, unsigned& lo, unsigned& hi) {
    asm("mov.b64 {%0, %1}, %2;" : "=r"(lo), "=r"(hi) : "l"(v));
}

// Diagonal-pair FFMA2 mm (see r11): W transposed [k][48], x [k][b].
// Thread tile: 3 row-pairs x 1 batch-pair, KH k-iters.
template<int KH>
__device__ __forceinline__ void gate_mmT(const float* __restrict__ w,
                                         const float* __restrict__ xp,
                                         float* __restrict__ gp)
{
    unsigned long long d0=0ull, a0=0ull, d1=0ull, a1=0ull, d2=0ull, a2=0ull;
    #pragma unroll 5
    for (int k = 0; k < KH; ++k) {
        uint2 xv = *(const uint2*)(xp + k * XSTR);
        unsigned long long xd = pk2(xv.x, xv.y);
        unsigned long long xs = pk2(xv.y, xv.x);
        unsigned long long w0 = *(const unsigned long long*)(w + k * 48);
        unsigned long long w1 = *(const unsigned long long*)(w + k * 48 + 2);
        unsigned long long w2 = *(const unsigned long long*)(w + k * 48 + 4);
        FMA2(d0, w0, xd); FMA2(a0, w0, xs);
        FMA2(d1, w1, xd); FMA2(a1, w1, xs);
        FMA2(d2, w2, xd); FMA2(a2, w2, xs);
    }
    unsigned dl, dh, al, ah;
    upk2(d0, dl, dh); upk2(a0, al, ah);
    *(unsigned long long*)(gp + 0 * GRS) = pk2(dl, al);
    *(unsigned long long*)(gp + 1 * GRS) = pk2(ah, dh);
    upk2(d1, dl, dh); upk2(a1, al, ah);
    *(unsigned long long*)(gp + 2 * GRS) = pk2(dl, al);
    *(unsigned long long*)(gp + 3 * GRS) = pk2(ah, dh);
    upk2(d2, dl, dh); upk2(a2, al, ah);
    *(unsigned long long*)(gp + 4 * GRS) = pk2(dl, al);
    *(unsigned long long*)(gp + 5 * GRS) = pk2(ah, dh);
}

__global__ void __launch_bounds__(NTHR, 1)
lstm_all_kernel(const float* __restrict__ inp,  const float* __restrict__ h0in,
                const float* __restrict__ c0in,
                const float* __restrict__ Wih0, const float* __restrict__ Whh0,
                const float* __restrict__ bih0, const float* __restrict__ bhh0,
                const float* __restrict__ Wih1, const float* __restrict__ Whh1,
                const float* __restrict__ bih1, const float* __restrict__ bhh1,
                const float* __restrict__ fcW,  const float* __restrict__ fcb,
                float* __restrict__ out)
{
    extern __shared__ float sm[];
    float* W0t   = sm + OFF_W0;
    float* W1t   = sm + OFF_W1;
    float* xh    = sm + OFF_XH;
    float* gb0   = sm + OFF_GB0;
    float* gb1   = sm + OFF_GB1;
    float* xac   = sm + OFF_XA;
    float* bias0 = sm + OFF_B0;
    float* bias1 = sm + OFF_B1;
    float* c0s   = sm + OFF_C0;
    float* c1s   = sm + OFF_C1;

    const int tid = threadIdx.x;
    const int bg  = blockIdx.x / NHG;
    const int hg  = blockIdx.x % NHG;
    const int b0  = bg * MB;
    const int hs  = hg * NHU;
    const uint32_t smb = (uint32_t)__cvta_generic_to_shared(sm);

    // role decode:
    //   layer1 mm: tid 0-511, cell=tid&63, ks1=tid>>6 (0..7)
    //   layer0 mm: tid 512-767, cell=(tid-512)&63, ks0=(tid-512)>>6 (0..3)
    //   xacc  mm: tid 0-127,   cell=tid&63, ksx=tid>>6 (0..1)
    const int cellA = tid & 63;
    const int bq2A  = cellA & 7;
    const int rpgA  = cellA >> 3;
    const int wofsA = 6 * rpgA;
    const int gofsA = 6 * rpgA * GRS + 2 * bq2A;
    const int ks1   = tid >> 6;            // valid when tid<512: 0..7
    const int tB    = tid - 512;
    const int cellB = tB & 63;
    const int bq2B  = cellB & 7;
    const int rpgB  = cellB >> 3;
    const int wofsB = 6 * rpgB;
    const int gofsB = 6 * rpgB * GRS + 2 * bq2B;
    const int ks0   = (tB >> 6) & 3;       // valid when tid>=512: 0..3

    // ---- resident weight slices (transposed [k][48]) ----
    for (int i = tid; i < NG * 300; i += NTHR) {
        int c = i / 300, k = i - c * 300;
        int gate = c / NHU, u = c - gate * NHU;
        int j = hs + u, row = gate * HID + j;
        float v = 0.f;
        if (j < HID) v = (k < INDIM) ? Wih0[row * INDIM + k] : Whh0[row * HID + (k - INDIM)];
        W0t[k * 48 + c] = v;
    }
    for (int i = tid; i < NG * 400; i += NTHR) {
        int c = i / 400, k = i - c * 400;
        int gate = c / NHU, u = c - gate * NHU;
        int j = hs + u, row = gate * HID + j;
        float v = 0.f;
        if (j < HID) v = (k < HID) ? Wih1[row * HID + k] : Whh1[row * HID + (k - HID)];
        W1t[k * 48 + c] = v;
    }
    if (tid < NG) {
        int gate = tid / NHU, u = tid - gate * NHU;
        int j = hs + u, row = gate * HID + j;
        bias0[tid] = (j < HID) ? bih0[row] + bhh0[row] : 0.f;
        bias1[tid] = (j < HID) ? bih1[row] + bhh1[row] : 0.f;
    }

    // ---- init c state, publish initial h ----
    if (tid < NHU * MB) {
        int e = tid, u = e >> 4, b = e & 15, j = hs + u;
        float cv0 = 0.f, cv1 = 0.f;
        if (j < HID) {
            cv0 = c0in[(b0 + b) * HID + j];
            cv1 = c0in[BATCH * HID + (b0 + b) * HID + j];
            g_ph0[1][j * BATCH + b0 + b] = h0in[(b0 + b) * HID + j];
            g_ph1[0][j * BATCH + b0 + b] = h0in[BATCH * HID + (b0 + b) * HID + j];
        }
        c0s[e] = cv0;
        c1s[e] = cv1;
    }

    // ---- prologue: stage x(0), xacc(0) ----
    {
        const float* xsrc = inp + (size_t)b0 * INDIM;
        for (int idx = tid; idx < MB * INDIM; idx += NTHR) {
            int b = idx / INDIM, k = idx - b * INDIM;
            xh[k * XSTR + b] = __ldg(xsrc + b * INDIM + k);
        }
    }
    __syncthreads();
    if (tid < 128)
        gate_mmT<50>(W0t + ks1 * 50 * 48 + wofsA, xh + ks1 * 50 * XSTR + 2 * bq2A,
                     xac + ks1 * GBS + gofsA);
    __syncthreads();

    unsigned* gbar = &g_bar[bg * 32];
    unsigned ep = 1;
    if (tid == 0) {
        bar_arrive(gbar);
        while (ld_acq(gbar) < ep * NHG) {}
    }
    __syncthreads();

    // ---- main loop: iter it = layer0(step it) + layer1(step it-1) ----
    for (int it = 0; it <= T_STEPS; ++it) {
        // async-stage h0(it-1) -> rows 100-299, h1(it-2) -> rows 300-499
        {
            const float* ph0 = g_ph0[(it + 1) & 1];
            const float* ph1 = g_ph1[(it + 1) & 1];
            int tot = (it >= 1) ? 1600 : 800;
            for (int idx = tid; idx < tot; idx += NTHR) {
                int a = idx >> 2, q = idx & 3;
                const float* src = (a < HID) ? (ph0 + a * BATCH)
                                             : (ph1 + (a - HID) * BATCH);
                cpa16(smb + (OFF_XH + (INDIM + a) * XSTR + q * 4) * 4,
                      src + b0 + q * 4);
            }
            cpa_wait();
        }
        __syncthreads();

        // balanced mm: every thread exactly 50 k-iters
        if (tid < 512) {
            if (it >= 1)                       // layer1 full K=400, ks1 0..7
                gate_mmT<50>(W1t + ks1 * 50 * 48 + wofsA,
                             xh + (INDIM + ks1 * 50) * XSTR + 2 * bq2A,
                             gb1 + ks1 * GBS + gofsA);
        } else {
            if (it < T_STEPS)                  // layer0 hh K=200, ks0 0..3
                gate_mmT<50>(W0t + (INDIM + ks0 * 50) * 48 + wofsB,
                             xh + (INDIM + ks0 * 50) * XSTR + 2 * bq2B,
                             gb0 + ks0 * GBS + gofsB);
        }
        __syncthreads();

        // ---- pointwise: layer0 on warps 0-5, layer1 on warps 8-13 ----
        if (it < T_STEPS && tid < 192) {
            int e = tid, u = e >> 4, b = e & 15, j = hs + u;
            float gv[4];
            #pragma unroll
            for (int g = 0; g < 4; ++g) {
                int rr = g * NHU + u;
                float v = bias0[rr];
                #pragma unroll
                for (int s = 0; s < 4; ++s) v += gb0[s * GBS + rr * GRS + b];
                v += xac[rr * GRS + b] + xac[GBS + rr * GRS + b];
                gv[g] = v;
            }
            float c = c0s[e];
            c = sigm(gv[1]) * c + sigm(gv[0]) * tanha(gv[2]);
            float h = sigm(gv[3]) * tanha(c);
            c0s[e] = c;
            if (j < HID) g_ph0[it & 1][j * BATCH + b0 + b] = h;
        }
        if (it >= 1 && tid >= 256 && tid < 448) {
            int e = tid - 256, u = e >> 4, b = e & 15, j = hs + u;
            float gv[4];
            #pragma unroll
            for (int g = 0; g < 4; ++g) {
                int rr = g * NHU + u;
                float v = bias1[rr];
                #pragma unroll
                for (int s = 0; s < 8; ++s) v += gb1[s * GBS + rr * GRS + b];
                gv[g] = v;
            }
            float c = c1s[e];
            c = sigm(gv[1]) * c + sigm(gv[0]) * tanha(gv[2]);
            float h = sigm(gv[3]) * tanha(c);
            c1s[e] = c;
            if (j < HID) {
                g_ph1[it & 1][j * BATCH + b0 + b] = h;
                g_y1[(size_t)(it - 1) * HID * BATCH + j * BATCH + b0 + b] = h;
            }
        }
        if (it == T_STEPS) break;
        __syncthreads();

        ep++;
        if (tid == 0) bar_arrive(gbar);

        // ---- barrier-shadow: stage x(it+1), xacc(it+1) ----
        if (it + 1 < T_STEPS) {
            const float* xsrc = inp + (size_t)(it + 1) * BATCH * INDIM + (size_t)b0 * INDIM;
            for (int idx = tid; idx < MB * INDIM; idx += NTHR) {
                int b = idx / INDIM, k = idx - b * INDIM;
                xh[k * XSTR + b] = __ldg(xsrc + b * INDIM + k);
            }
            __syncthreads();
            if (tid < 128)
                gate_mmT<50>(W0t + ks1 * 50 * 48 + wofsA, xh + ks1 * 50 * XSTR + 2 * bq2A,
                             xac + ks1 * GBS + gofsA);
        }

        if (tid == 0) { while (ld_acq(gbar) < ep * NHG) {} }
        __syncthreads();
    }

    // final layer1 pw (tid 256-447) must be visible to epilogue readers
    __syncthreads();

    // ---- epilogue: hn, cn ----
    if (tid < NHU * MB) {
        int e = tid, u = e >> 4, b = e & 15, j = hs + u;
        if (j < HID) {
            out[HN_OFF + (b0 + b) * HID + j]               = __ldcg(&g_ph0[(T_STEPS - 1) & 1][j * BATCH + b0 + b]);
            out[HN_OFF + BATCH * HID + (b0 + b) * HID + j] = __ldcg(&g_ph1[T_STEPS & 1][j * BATCH + b0 + b]);
            out[CN_OFF + (b0 + b) * HID + j]               = c0s[e];
            out[CN_OFF + BATCH * HID + (b0 + b) * HID + j] = c1s[e];
        }
    }
    __syncthreads();

    // ---- global barrier before FC ----
    if (tid == 0) {
        bar_arrive(&g_gbar);
        while (ld_acq(&g_gbar) < NCTA) {}
    }
    __syncthreads();

    // ---- FC phase: out[t,b,c] = fcb[c] + sum_h fcW[c][h] * y1[t,h,b] ----
    {
        float* fws = sm + OFF_FW;
        float* fbs = sm + OFF_FB;
        float* ys  = sm + OFF_YS;
        for (int i = tid; i < NCLS * HID; i += NTHR) fws[i] = fcW[i];
        if (tid < NCLS) fbs[tid] = fcb[tid];
        __syncthreads();

        const int bqf = (tid & 31) * 4;
        const int cg  = tid >> 5;              // 0..23
        for (int tt = 0; tt < 8; ++tt) {
            int t = blockIdx.x * 8 + tt;
            if (t >= T_STEPS) break;
            const float* y = g_y1 + (size_t)t * HID * BATCH;
            float acc[2][4][4];
            #pragma unroll
            for (int qi = 0; qi < 2; qi++) {
                int cq = cg + 24 * qi;
                #pragma unroll
                for (int jc = 0; jc < 4; jc++) {
                    float bv = (cq < 25) ? fbs[cq * 4 + jc] : 0.f;
                    #pragma unroll
                    for (int jb = 0; jb < 4; jb++) acc[qi][jc][jb] = bv;
                }
            }
            for (int kc = 0; kc < 4; ++kc) {
                __syncthreads();
                for (int i = tid; i < 50 * 32; i += NTHR) {
                    int k = i >> 5, q = i & 31;
                    *(float4*)&ys[k * 128 + q * 4] =
                        __ldcg((const float4*)(y + (size_t)(kc * 50 + k) * BATCH + q * 4));
                }
                __syncthreads();
                for (int k = 0; k < 50; ++k) {
                    float4 yv = *(const float4*)&ys[k * 128 + bqf];
                    #pragma unroll
                    for (int qi = 0; qi < 2; qi++) {
                        int cq = cg + 24 * qi;
                        if (cq < 25) {
                            #pragma unroll
                            for (int jc = 0; jc < 4; jc++) {
                                float w = fws[(cq * 4 + jc) * HID + kc * 50 + k];
                                acc[qi][jc][0] = fmaf(w, yv.x, acc[qi][jc][0]);
                                acc[qi][jc][1] = fmaf(w, yv.y, acc[qi][jc][1]);
                                acc[qi][jc][2] = fmaf(w, yv.z, acc[qi][jc][2]);
                                acc[qi][jc][3] = fmaf(w, yv.w, acc[qi][jc][3]);
                            }
                        }
                    }
                }
            }
            float* o = out + (size_t)t * BATCH * NCLS;
            #pragma unroll
            for (int qi = 0; qi < 2; qi++) {
                int cq = cg + 24 * qi;
                if (cq < 25) {
                    #pragma unroll
                    for (int jb = 0; jb < 4; jb++) {
                        float4 v = make_float4(acc[qi][0][jb], acc[qi][1][jb],
                                               acc[qi][2][jb], acc[qi][3][jb]);
                        *(float4*)(o + (bqf + jb) * NCLS + cq * 4) = v;
                    }
                }
            }
        }
    }

    // ---- reset-free counter cleanup ----
    __syncthreads();
    if (tid == 0) {
        bar_arrive(&g_ack);
        if (blockIdx.x == 0) {
            while (ld_acq(&g_ack) < NCTA) {}
            for (int i = 0; i < NBG; i++) *(volatile unsigned*)&g_bar[i * 32] = 0u;
            *(volatile unsigned*)&g_gbar = 0u;
            *(volatile unsigned*)&g_ack  = 0u;
        }
    }
}

extern "C" void kernel_launch(void* const* d_in, const int* in_sizes, int n_in,
                              void* d_out, int out_size)
{
    (void)in_sizes; (void)n_in; (void)out_size;
    const float* inp  = (const float*)d_in[0];
    const float* h0   = (const float*)d_in[1];
    const float* c0   = (const float*)d_in[2];
    const float* Wih0 = (const float*)d_in[3];
    const float* Whh0 = (const float*)d_in[4];
    const float* bih0 = (const float*)d_in[5];
    const float* bhh0 = (const float*)d_in[6];
    const float* Wih1 = (const float*)d_in[7];
    const float* Whh1 = (const float*)d_in[8];
    const float* bih1 = (const float*)d_in[9];
    const float* bhh1 = (const float*)d_in[10];
    const float* fcW  = (const float*)d_in[11];
    const float* fcb  = (const float*)d_in[12];
    float* out = (float*)d_out;

    cudaFuncSetAttribute(lstm_all_kernel,
                         cudaFuncAttributeMaxDynamicSharedMemorySize, SMEM_BYTES);
    lstm_all_kernel<<<NCTA, NTHR, SMEM_BYTES>>>(inp, h0, c0,
                                                Wih0, Whh0, bih0, bhh0,
                                                Wih1, Whh1, bih1, bhh1,
                                                fcW, fcb, out);
}

// round 13
// speedup vs baseline: 1.1915x; 1.0973x over previous
#include <cuda_runtime.h>
#include <cstdint>
#include <cstddef>

#define T_STEPS 1024
#define BATCH   128
#define INDIM   100
#define HID     200
#define NCLS    100
#define NBG     8
#define MB      16
#define NHG     17
#define NHU     12
#define NG      48
#define NTHR    768
#define NCTA    (NBG*NHG)   // 136
#define XSTR    20
#define GRS     18
#define GBS     (NG*GRS)    // 864

#define HN_OFF  (T_STEPS*BATCH*NCLS)
#define CN_OFF  (HN_OFF + 2*BATCH*HID)

// ---- smem float offsets ----
#define OFF_W0  0                        // W0 transposed [300][48]
#define OFF_W1  14400                    // W1 transposed [400][48]
#define OFF_XH  33600                    // [500][XSTR]
#define OFF_GB0 43600                    // [4][GBS]
#define OFF_GB1 47056                    // [8][GBS]
#define OFF_XA  53968                    // [4][GBS]
#define OFF_B0  57424
#define OFF_B1  57472
#define OFF_C0  57520
#define OFF_C1  57712
#define SMEM_FLOATS 57920
#define SMEM_BYTES  (SMEM_FLOATS*4)      // 231,680 B

// FC-phase smem reuse
#define OFF_FW  0
#define OFF_FB  20000
#define OFF_YS  20128

__device__ __align__(256) float g_ph0[2][HID*BATCH];
__device__ __align__(256) float g_ph1[2][HID*BATCH];
__device__ __align__(256) float g_y1[(size_t)T_STEPS*HID*BATCH];
__device__ unsigned g_bar[NBG*32];
__device__ unsigned g_gbar;
__device__ unsigned g_ack;

__device__ __forceinline__ float tanha(float x) {
    float r;
    asm("tanh.approx.f32 %0, %1;" : "=f"(r) : "f"(x));
    return r;
}
__device__ __forceinline__ float sigm(float x) {
    return fmaf(0.5f, tanha(0.5f * x), 0.5f);
}
__device__ __forceinline__ void bar_arrive(unsigned* p) {
    unsigned one = 1u;
    asm volatile("red.release.gpu.global.add.u32 [%0], %1;" :: "l"(p), "r"(one) : "memory");
}
__device__ __forceinline__ unsigned ld_acq(const unsigned* p) {
    unsigned v;
    asm volatile("ld.acquire.gpu.global.u32 %0, [%1];" : "=r"(v) : "l"(p) : "memory");
    return v;
}
__device__ __forceinline__ void cpa16(uint32_t dst, const void* src) {
    asm volatile("cp.async.cg.shared.global [%0], [%1], 16;" :: "r"(dst), "l"(src) : "memory");
}
#define CPA_COMMIT() asm volatile("cp.async.commit_group;" ::: "memory")
#define CPA_WAIT0()  asm volatile("cp.async.wait_group 0;" ::: "memory")

#define FMA2(acc, w, x) \
    asm("fma.rn.f32x2 %0, %1, %2, %0;" : "+l"(acc) : "l"(w), "l"(x))
__device__ __forceinline__ unsigned long long pk2(unsigned lo, unsigned hi) {
    unsigned long long d;
    asm("mov.b64 %0, {%1, %2};" : "=l"(d) : "r"(lo), "r"(hi));
    return d;
}
__device__ __forceinline__ void upk2(unsigned long long v, unsigned& lo, unsigned& hi) {
    asm("mov.b64 {%0, %1}, %2;" : "=r"(lo), "=r"(hi) : "l"(v));
}

// Diagonal-pair FFMA2 mm: W transposed [k][48], x [k][b].
// Thread tile: 3 row-pairs x 1 batch-pair, KH k-iters.
template<int KH>
__device__ __forceinline__ void gate_mmT(const float* __restrict__ w,
                                         const float* __restrict__ xp,
                                         float* __restrict__ gp)
{
    unsigned long long d0=0ull, a0=0ull, d1=0ull, a1=0ull, d2=0ull, a2=0ull;
    #pragma unroll 5
    for (int k = 0; k < KH; ++k) {
        uint2 xv = *(const uint2*)(xp + k * XSTR);
        unsigned long long xd = pk2(xv.x, xv.y);
        unsigned long long xs = pk2(xv.y, xv.x);
        unsigned long long w0 = *(const unsigned long long*)(w + k * 48);
        unsigned long long w1 = *(const unsigned long long*)(w + k * 48 + 2);
        unsigned long long w2 = *(const unsigned long long*)(w + k * 48 + 4);
        FMA2(d0, w0, xd); FMA2(a0, w0, xs);
        FMA2(d1, w1, xd); FMA2(a1, w1, xs);
        FMA2(d2, w2, xd); FMA2(a2, w2, xs);
    }
    unsigned dl, dh, al, ah;
    upk2(d0, dl, dh); upk2(a0, al, ah);
    *(unsigned long long*)(gp + 0 * GRS) = pk2(dl, al);
    *(unsigned long long*)(gp + 1 * GRS) = pk2(ah, dh);
    upk2(d1, dl, dh); upk2(a1, al, ah);
    *(unsigned long long*)(gp + 2 * GRS) = pk2(dl, al);
    *(unsigned long long*)(gp + 3 * GRS) = pk2(ah, dh);
    upk2(d2, dl, dh); upk2(a2, al, ah);
    *(unsigned long long*)(gp + 4 * GRS) = pk2(dl, al);
    *(unsigned long long*)(gp + 5 * GRS) = pk2(ah, dh);
}

__global__ void __launch_bounds__(NTHR, 1)
lstm_all_kernel(const float* __restrict__ inp,  const float* __restrict__ h0in,
                const float* __restrict__ c0in,
                const float* __restrict__ Wih0, const float* __restrict__ Whh0,
                const float* __restrict__ bih0, const float* __restrict__ bhh0,
                const float* __restrict__ Wih1, const float* __restrict__ Whh1,
                const float* __restrict__ bih1, const float* __restrict__ bhh1,
                const float* __restrict__ fcW,  const float* __restrict__ fcb,
                float* __restrict__ out)
{
    extern __shared__ float sm[];
    float* W0t   = sm + OFF_W0;
    float* W1t   = sm + OFF_W1;
    float* xh    = sm + OFF_XH;
    float* gb0   = sm + OFF_GB0;
    float* gb1   = sm + OFF_GB1;
    float* xac   = sm + OFF_XA;
    float* bias0 = sm + OFF_B0;
    float* bias1 = sm + OFF_B1;
    float* c0s   = sm + OFF_C0;
    float* c1s   = sm + OFF_C1;

    const int tid = threadIdx.x;
    const int bg  = blockIdx.x / NHG;
    const int hg  = blockIdx.x % NHG;
    const int b0  = bg * MB;
    const int hs  = hg * NHU;
    const uint32_t smb = (uint32_t)__cvta_generic_to_shared(sm);

    // role decode
    const int cellA = tid & 63;
    const int bq2A  = cellA & 7;
    const int rpgA  = cellA >> 3;
    const int wofsA = 6 * rpgA;
    const int gofsA = 6 * rpgA * GRS + 2 * bq2A;
    const int ks1   = tid >> 6;            // layer1 ksplit (tid<512): 0..7
    const int ksx   = ks1 & 3;             // xacc ksplit (tid<256): 0..3
    const int tB    = tid - 512;
    const int cellB = tB & 63;
    const int bq2B  = cellB & 7;
    const int rpgB  = cellB >> 3;
    const int wofsB = 6 * rpgB;
    const int gofsB = 6 * rpgB * GRS + 2 * bq2B;
    const int ks0   = (tB >> 6) & 3;       // layer0 ksplit (tid>=512): 0..3

    // ---- resident weight slices (transposed [k][48]) ----
    for (int i = tid; i < NG * 300; i += NTHR) {
        int c = i / 300, k = i - c * 300;
        int gate = c / NHU, u = c - gate * NHU;
        int j = hs + u, row = gate * HID + j;
        float v = 0.f;
        if (j < HID) v = (k < INDIM) ? Wih0[row * INDIM + k] : Whh0[row * HID + (k - INDIM)];
        W0t[k * 48 + c] = v;
    }
    for (int i = tid; i < NG * 400; i += NTHR) {
        int c = i / 400, k = i - c * 400;
        int gate = c / NHU, u = c - gate * NHU;
        int j = hs + u, row = gate * HID + j;
        float v = 0.f;
        if (j < HID) v = (k < HID) ? Wih1[row * HID + k] : Whh1[row * HID + (k - HID)];
        W1t[k * 48 + c] = v;
    }
    if (tid < NG) {
        int gate = tid / NHU, u = tid - gate * NHU;
        int j = hs + u, row = gate * HID + j;
        bias0[tid] = (j < HID) ? bih0[row] + bhh0[row] : 0.f;
        bias1[tid] = (j < HID) ? bih1[row] + bhh1[row] : 0.f;
    }

    // ---- init c state, publish initial h ----
    if (tid < NHU * MB) {
        int e = tid, u = e >> 4, b = e & 15, j = hs + u;
        float cv0 = 0.f, cv1 = 0.f;
        if (j < HID) {
            cv0 = c0in[(b0 + b) * HID + j];
            cv1 = c0in[BATCH * HID + (b0 + b) * HID + j];
            g_ph0[1][j * BATCH + b0 + b] = h0in[(b0 + b) * HID + j];
            g_ph1[0][j * BATCH + b0 + b] = h0in[BATCH * HID + (b0 + b) * HID + j];
        }
        c0s[e] = cv0;
        c1s[e] = cv1;
    }

    // ---- prologue: stage x(0), xacc(0) ----
    {
        const float* xsrc = inp + (size_t)b0 * INDIM;
        for (int idx = tid; idx < MB * INDIM; idx += NTHR) {
            int b = idx / INDIM, k = idx - b * INDIM;
            xh[k * XSTR + b] = __ldg(xsrc + b * INDIM + k);
        }
    }
    __syncthreads();
    if (tid < 256)
        gate_mmT<25>(W0t + ksx * 25 * 48 + wofsA, xh + ksx * 25 * XSTR + 2 * bq2A,
                     xac + ksx * GBS + gofsA);
    __syncthreads();

    unsigned* gbar = &g_bar[bg * 32];
    unsigned ep = 1;
    if (tid == 0) {
        bar_arrive(gbar);
        while (ld_acq(gbar) < ep * NHG) {}
    }
    __syncthreads();

    // ---- main loop: iter it = layer0(step it) + layer1(step it-1) ----
    for (int it = 0; it <= T_STEPS; ++it) {
        // split async staging + mm:
        //   h0 rows 100-299: issued+consumed by tid<256 (layer1 ks0-3) and tid>=512 (layer0hh)
        //   h1 rows 300-499: issued+consumed by tid 256-511 (layer1 ks4-7)
        const float* ph0 = g_ph0[(it + 1) & 1];
        const float* ph1 = g_ph1[(it + 1) & 1];
        if (tid < 256 || tid >= 512) {
            int st = (tid < 256) ? tid : (tid - 256);   // 0..511
            for (int idx = st; idx < 800; idx += 512) {
                int a = idx >> 2, q = idx & 3;
                cpa16(smb + (OFF_XH + (INDIM + a) * XSTR + q * 4) * 4,
                      ph0 + a * BATCH + b0 + q * 4);
            }
            CPA_COMMIT();
            CPA_WAIT0();
            asm volatile("bar.sync 2, 512;" ::: "memory");
            if (tid < 256) {
                if (it >= 1)                   // layer1 lower half (ks1 0..3, h0 rows)
                    gate_mmT<50>(W1t + ks1 * 50 * 48 + wofsA,
                                 xh + (INDIM + ks1 * 50) * XSTR + 2 * bq2A,
                                 gb1 + ks1 * GBS + gofsA);
            } else {
                if (it < T_STEPS)              // layer0 hh (h0 rows)
                    gate_mmT<50>(W0t + (INDIM + ks0 * 50) * 48 + wofsB,
                                 xh + (INDIM + ks0 * 50) * XSTR + 2 * bq2B,
                                 gb0 + ks0 * GBS + gofsB);
            }
        } else {
            if (it >= 1) {
                int st = tid - 256;            // 0..255
                for (int idx = st; idx < 800; idx += 256) {
                    int a = idx >> 2, q = idx & 3;   // rows 300+a/4... a=idx>>2 in 0..199
                    cpa16(smb + (OFF_XH + (INDIM + HID + a) * XSTR + q * 4) * 4,
                          ph1 + a * BATCH + b0 + q * 4);
                }
            }
            CPA_COMMIT();
            CPA_WAIT0();
            asm volatile("bar.sync 3, 256;" ::: "memory");
            if (it >= 1)                       // layer1 upper half (ks1 4..7, h1 rows)
                gate_mmT<50>(W1t + ks1 * 50 * 48 + wofsA,
                             xh + (INDIM + ks1 * 50) * XSTR + 2 * bq2A,
                             gb1 + ks1 * GBS + gofsA);
        }
        __syncthreads();

        // ---- pointwise (MUFU.TANH): layer0 tid<192, layer1 tid 256-447 ----
        if (it < T_STEPS && tid < 192) {
            int e = tid, u = e >> 4, b = e & 15, j = hs + u;
            float gv[4];
            #pragma unroll
            for (int g = 0; g < 4; ++g) {
                int rr = g * NHU + u;
                float v = bias0[rr];
                #pragma unroll
                for (int s = 0; s < 4; ++s)
                    v += gb0[s * GBS + rr * GRS + b] + xac[s * GBS + rr * GRS + b];
                gv[g] = v;
            }
            float c = c0s[e];
            c = sigm(gv[1]) * c + sigm(gv[0]) * tanha(gv[2]);
            float h = sigm(gv[3]) * tanha(c);
            c0s[e] = c;
            if (j < HID) g_ph0[it & 1][j * BATCH + b0 + b] = h;
        }
        if (it >= 1 && tid >= 256 && tid < 448) {
            int e = tid - 256, u = e >> 4, b = e & 15, j = hs + u;
            float gv[4];
            #pragma unroll
            for (int g = 0; g < 4; ++g) {
                int rr = g * NHU + u;
                float v = bias1[rr];
                #pragma unroll
                for (int s = 0; s < 8; ++s) v += gb1[s * GBS + rr * GRS + b];
                gv[g] = v;
            }
            float c = c1s[e];
            c = sigm(gv[1]) * c + sigm(gv[0]) * tanha(gv[2]);
            float h = sigm(gv[3]) * tanha(c);
            c1s[e] = c;
            if (j < HID) {
                g_ph1[it & 1][j * BATCH + b0 + b] = h;
                g_y1[(size_t)(it - 1) * HID * BATCH + j * BATCH + b0 + b] = h;
            }
        }
        if (it == T_STEPS) break;
        __syncthreads();

        ep++;
        if (tid == 0) bar_arrive(gbar);

        // ---- barrier-shadow: stage x(it+1), xacc(it+1); poll on tid 767 ----
        if (it + 1 < T_STEPS) {
            const float* xsrc = inp + (size_t)(it + 1) * BATCH * INDIM + (size_t)b0 * INDIM;
            for (int idx = tid; idx < MB * INDIM; idx += NTHR) {
                int b = idx / INDIM, k = idx - b * INDIM;
                xh[k * XSTR + b] = __ldg(xsrc + b * INDIM + k);
            }
            __syncthreads();
            if (tid < 256)
                gate_mmT<25>(W0t + ksx * 25 * 48 + wofsA, xh + ksx * 25 * XSTR + 2 * bq2A,
                             xac + ksx * GBS + gofsA);
        }

        if (tid == NTHR - 1) { while (ld_acq(gbar) < ep * NHG) {} }
        __syncthreads();
    }

    // final layer1 pw (tid 256-447) must be visible to epilogue readers
    __syncthreads();

    // ---- epilogue: hn, cn ----
    if (tid < NHU * MB) {
        int e = tid, u = e >> 4, b = e & 15, j = hs + u;
        if (j < HID) {
            out[HN_OFF + (b0 + b) * HID + j]               = __ldcg(&g_ph0[(T_STEPS - 1) & 1][j * BATCH + b0 + b]);
            out[HN_OFF + BATCH * HID + (b0 + b) * HID + j] = __ldcg(&g_ph1[T_STEPS & 1][j * BATCH + b0 + b]);
            out[CN_OFF + (b0 + b) * HID + j]               = c0s[e];
            out[CN_OFF + BATCH * HID + (b0 + b) * HID + j] = c1s[e];
        }
    }
    __syncthreads();

    // ---- global barrier before FC ----
    if (tid == 0) {
        bar_arrive(&g_gbar);
        while (ld_acq(&g_gbar) < NCTA) {}
    }
    __syncthreads();

    // ---- FC phase: out[t,b,c] = fcb[c] + sum_h fcW[c][h] * y1[t,h,b] ----
    {
        float* fws = sm + OFF_FW;
        float* fbs = sm + OFF_FB;
        float* ys  = sm + OFF_YS;
        for (int i = tid; i < NCLS * HID; i += NTHR) fws[i] = fcW[i];
        if (tid < NCLS) fbs[tid] = fcb[tid];
        __syncthreads();

        const int bqf = (tid & 31) * 4;
        const int cg  = tid >> 5;              // 0..23
        for (int tt = 0; tt < 8; ++tt) {
            int t = blockIdx.x * 8 + tt;
            if (t >= T_STEPS) break;
            const float* y = g_y1 + (size_t)t * HID * BATCH;
            float acc[2][4][4];
            #pragma unroll
            for (int qi = 0; qi < 2; qi++) {
                int cq = cg + 24 * qi;
                #pragma unroll
                for (int jc = 0; jc < 4; jc++) {
                    float bv = (cq < 25) ? fbs[cq * 4 + jc] : 0.f;
                    #pragma unroll
                    for (int jb = 0; jb < 4; jb++) acc[qi][jc][jb] = bv;
                }
            }
            for (int kc = 0; kc < 4; ++kc) {
                __syncthreads();
                for (int i = tid; i < 50 * 32; i += NTHR) {
                    int k = i >> 5, q = i & 31;
                    *(float4*)&ys[k * 128 + q * 4] =
                        __ldcg((const float4*)(y + (size_t)(kc * 50 + k) * BATCH + q * 4));
                }
                __syncthreads();
                for (int k = 0; k < 50; ++k) {
                    float4 yv = *(const float4*)&ys[k * 128 + bqf];
                    #pragma unroll
                    for (int qi = 0; qi < 2; qi++) {
                        int cq = cg + 24 * qi;
                        if (cq < 25) {
                            #pragma unroll
                            for (int jc = 0; jc < 4; jc++) {
                                float w = fws[(cq * 4 + jc) * HID + kc * 50 + k];
                                acc[qi][jc][0] = fmaf(w, yv.x, acc[qi][jc][0]);
                                acc[qi][jc][1] = fmaf(w, yv.y, acc[qi][jc][1]);
                                acc[qi][jc][2] = fmaf(w, yv.z, acc[qi][jc][2]);
                                acc[qi][jc][3] = fmaf(w, yv.w, acc[qi][jc][3]);
                            }
                        }
                    }
                }
            }
            float* o = out + (size_t)t * BATCH * NCLS;
            #pragma unroll
            for (int qi = 0; qi < 2; qi++) {
                int cq = cg + 24 * qi;
                if (cq < 25) {
                    #pragma unroll
                    for (int jb = 0; jb < 4; jb++) {
                        float4 v = make_float4(acc[qi][0][jb], acc[qi][1][jb],
                                               acc[qi][2][jb], acc[qi][3][jb]);
                        *(float4*)(o + (bqf + jb) * NCLS + cq * 4) = v;
                    }
                }
            }
        }
    }

    // ---- reset-free counter cleanup ----
    __syncthreads();
    if (tid == 0) {
        bar_arrive(&g_ack);
        if (blockIdx.x == 0) {
            while (ld_acq(&g_ack) < NCTA) {}
            for (int i = 0; i < NBG; i++) *(volatile unsigned*)&g_bar[i * 32] = 0u;
            *(volatile unsigned*)&g_gbar = 0u;
            *(volatile unsigned*)&g_ack  = 0u;
        }
    }
}

extern "C" void kernel_launch(void* const* d_in, const int* in_sizes, int n_in,
                              void* d_out, int out_size)
{
    (void)in_sizes; (void)n_in; (void)out_size;
    const float* inp  = (const float*)d_in[0];
    const float* h0   = (const float*)d_in[1];
    const float* c0   = (const float*)d_in[2];
    const float* Wih0 = (const float*)d_in[3];
    const float* Whh0 = (const float*)d_in[4];
    const float* bih0 = (const float*)d_in[5];
    const float* bhh0 = (const float*)d_in[6];
    const float* Wih1 = (const float*)d_in[7];
    const float* Whh1 = (const float*)d_in[8];
    const float* bih1 = (const float*)d_in[9];
    const float* bhh1 = (const float*)d_in[10];
    const float* fcW  = (const float*)d_in[11];
    const float* fcb  = (const float*)d_in[12];
    float* out = (float*)d_out;

    cudaFuncSetAttribute(lstm_all_kernel,
                         cudaFuncAttributeMaxDynamicSharedMemorySize, SMEM_BYTES);
    lstm_all_kernel<<<NCTA, NTHR, SMEM_BYTES>>>(inp, h0, c0,
                                                Wih0, Whh0, bih0, bhh0,
                                                Wih1, Whh1, bih1, bhh1,
                                                fcW, fcb, out);
}